// round 1
// baseline (speedup 1.0000x reference)
#include <cuda_runtime.h>
#include <math.h>

// ---------------------------------------------------------------------------
// Problem constants
// ---------------------------------------------------------------------------
namespace {
constexpr int N_Q   = 20000;   // queries
constexpr int S_SUP = 20000;   // supports
constexpr int NEI   = 30;      // neighbors
constexpr int KP    = 15;      // kernel points
constexpr int NQL   = 4;       // query LRFs
constexpr int CIN_  = 128;
constexpr int FDIM_ = 256;     // 2*CIN
constexpr int COUT_ = 256;
constexpr int BIGK  = KP * FDIM_;   // 3840
constexpr float INV_EXT = 20.0f;    // 1 / 0.05
}

// Scratch: weighted tensor, layout [n][k*256 + q*64 + c]  (row-major [N, 3840])
__device__ float g_weighted[(size_t)N_Q * BIGK];

// ---------------------------------------------------------------------------
// Stage 1: per-query geometry, LRF features, neighbor-weighted reduction
// One block per query, 128 threads.
// ---------------------------------------------------------------------------
__global__ __launch_bounds__(128) void stage1_kernel(
    const float* __restrict__ q_pts,      // [N,3]
    const float* __restrict__ s_pts,      // [S,3]
    const int*   __restrict__ neighb_inds,// [N,30]
    const float* __restrict__ x,          // [S,128]
    const float* __restrict__ q_lrf,      // [N,4,3,3]
    const float* __restrict__ s_lrf,      // [S,4,3,3]
    const float* __restrict__ kpts,       // [15,3]
    const float* __restrict__ W_lrf,      // [36,32]
    const float* __restrict__ b_lrf)      // [32]
{
    __shared__ __align__(16) float ql[36];
    __shared__ __align__(16) float kp_s[48];
    __shared__ __align__(16) float Wl[36 * 32];
    __shared__ __align__(16) float bl[32];
    // w_sm[k][m][q]: stride per k = 120, padded to 16 k-rows (row 15 zeroed)
    __shared__ __align__(16) float w_sm[16 * 120];
    // f_sm[m][q*68 + c], c in [0,64): x part c<32, lrf part c>=32. Pad stride 68.
    __shared__ __align__(16) float f_sm[30 * 272];
    __shared__ int   ind_s[30];
    __shared__ float qp[3];

    const int n   = blockIdx.x;
    const int tid = threadIdx.x;

    if (tid < 36) ql[tid]    = q_lrf[(size_t)n * 36 + tid];
    if (tid < 45) kp_s[tid]  = kpts[tid];
    if (tid < 3)  qp[tid]    = q_pts[(size_t)n * 3 + tid];
    if (tid < 32) bl[tid]    = b_lrf[tid];
    if (tid < 30) ind_s[tid] = neighb_inds[(size_t)n * NEI + tid];
    for (int i = tid; i < 36 * 32; i += 128) Wl[i] = W_lrf[i];
    if (tid < 120) w_sm[15 * 120 + tid] = 0.0f;  // pad row for phase-2 8-wide tile
    __syncthreads();

    // ---- x gather into f_sm (c < 32 halves of each q group), coalesced ----
    #pragma unroll 1
    for (int i = tid; i < NEI * CIN_; i += 128) {
        const int m  = i >> 7;        // / 128
        const int qc = i & 127;       // q*32 + c
        const int ind = ind_s[m];
        float v = 0.0f;
        if (ind < S_SUP) v = x[(size_t)ind * CIN_ + qc];
        f_sm[m * 272 + (qc >> 5) * 68 + (qc & 31)] = v;
    }

    // ---- per-(neighbor, q-LRF) geometry + LRF features: 120 threads ----
    if (tid < 120) {
        const int m = tid >> 2;
        const int q = tid & 3;
        const int ind = ind_s[m];
        const bool valid = (ind < S_SUP);
        const int indc = valid ? ind : 0;
        const float* qlr = &ql[q * 9];   // ql[q][i][j] at qlr[i*3+j]

        // neighbor offset
        const float nb0 = s_pts[(size_t)indc * 3 + 0] - qp[0];
        const float nb1 = s_pts[(size_t)indc * 3 + 1] - qp[1];
        const float nb2 = s_pts[(size_t)indc * 3 + 2] - qp[2];
        // aligned[j] = sum_i nb[i] * ql[q][i][j]
        const float a0 = nb0 * qlr[0] + nb1 * qlr[3] + nb2 * qlr[6];
        const float a1 = nb0 * qlr[1] + nb1 * qlr[4] + nb2 * qlr[7];
        const float a2 = nb0 * qlr[2] + nb1 * qlr[5] + nb2 * qlr[8];

        // KP influence weights
        #pragma unroll
        for (int k = 0; k < KP; k++) {
            const float d0 = a0 - kp_s[k * 3 + 0];
            const float d1 = a1 - kp_s[k * 3 + 1];
            const float d2 = a2 - kp_s[k * 3 + 2];
            float w = 1.0f - sqrtf(d0 * d0 + d1 * d1 + d2 * d2) * INV_EXT;
            w = fmaxf(w, 0.0f);
            w_sm[k * 120 + m * 4 + q] = valid ? w : 0.0f;
        }

        // support LRF row (4 LRFs x 3 x 3 = 36 floats)
        float sl[36];
        {
            const float4* p = reinterpret_cast<const float4*>(s_lrf + (size_t)indc * 36);
            #pragma unroll
            for (int t = 0; t < 9; t++) {
                const float4 v = p[t];
                sl[t * 4 + 0] = v.x; sl[t * 4 + 1] = v.y;
                sl[t * 4 + 2] = v.z; sl[t * 4 + 3] = v.w;
            }
        }
        // aligned_lrf[s*9+i*3+j] = sum_kk ql[q][kk][i] * sl[s][kk][j]
        float al[36];
        #pragma unroll
        for (int s = 0; s < 4; s++)
            #pragma unroll
            for (int i = 0; i < 3; i++)
                #pragma unroll
                for (int j = 0; j < 3; j++) {
                    al[s * 9 + i * 3 + j] =
                        qlr[0 * 3 + i] * sl[s * 9 + 0 * 3 + j] +
                        qlr[1 * 3 + i] * sl[s * 9 + 1 * 3 + j] +
                        qlr[2 * 3 + i] * sl[s * 9 + 2 * 3 + j];
                }
        // lrf_features = al @ W_lrf + b_lrf  (36 x 32 GEMV)
        float4 lf[8];
        #pragma unroll
        for (int c4 = 0; c4 < 8; c4++) {
            lf[c4].x = bl[c4 * 4 + 0]; lf[c4].y = bl[c4 * 4 + 1];
            lf[c4].z = bl[c4 * 4 + 2]; lf[c4].w = bl[c4 * 4 + 3];
        }
        #pragma unroll
        for (int t = 0; t < 36; t++) {
            const float a = al[t];
            const float4* wr = reinterpret_cast<const float4*>(&Wl[t * 32]);
            #pragma unroll
            for (int c4 = 0; c4 < 8; c4++) {
                const float4 wv = wr[c4];
                lf[c4].x += a * wv.x; lf[c4].y += a * wv.y;
                lf[c4].z += a * wv.z; lf[c4].w += a * wv.w;
            }
        }
        if (!valid) {
            #pragma unroll
            for (int c4 = 0; c4 < 8; c4++) lf[c4] = make_float4(0.f, 0.f, 0.f, 0.f);
        }
        float4* frow = reinterpret_cast<float4*>(&f_sm[m * 272 + q * 68 + 32]);
        #pragma unroll
        for (int c4 = 0; c4 < 8; c4++) frow[c4] = lf[c4];
    }
    __syncthreads();

    // ---- phase 2: weighted[q][k][c] = sum_m w[q][k][m] * f[m][q][c] ----
    // thread tile: 8 k-rows (half) x 4 c (one float4), fixed q.
    const int half = tid >> 6;          // 0 -> k 0..7, 1 -> k 8..15 (15 padded)
    const int q2   = (tid >> 4) & 3;
    const int c4   = tid & 15;
    const int k0   = half * 8;

    float4 acc[8];
    #pragma unroll
    for (int i = 0; i < 8; i++) acc[i] = make_float4(0.f, 0.f, 0.f, 0.f);

    #pragma unroll 1
    for (int m = 0; m < NEI; m++) {
        const float4 f4 = *reinterpret_cast<const float4*>(&f_sm[m * 272 + q2 * 68 + c4 * 4]);
        const float* wp = &w_sm[k0 * 120 + m * 4 + q2];
        #pragma unroll
        for (int kl = 0; kl < 8; kl++) {
            const float wv = wp[kl * 120];
            acc[kl].x += wv * f4.x; acc[kl].y += wv * f4.y;
            acc[kl].z += wv * f4.z; acc[kl].w += wv * f4.w;
        }
    }

    float* outp = g_weighted + (size_t)n * BIGK;
    #pragma unroll
    for (int kl = 0; kl < 8; kl++) {
        const int k = k0 + kl;
        if (k < KP)
            *reinterpret_cast<float4*>(&outp[k * 256 + q2 * 64 + c4 * 4]) = acc[kl];
    }
}

// ---------------------------------------------------------------------------
// Stage 2: out[N,256] = weighted[N,3840] @ weights[3840,256] + bias, leaky
// Classic 128x128x8 fp32 SIMT GEMM, 8x8 per-thread micro-tile.
// ---------------------------------------------------------------------------
namespace {
constexpr int BM = 128, BN = 128, BK = 8;
}

__global__ __launch_bounds__(256) void gemm_kernel(
    const float* __restrict__ Bw,    // weights flattened [3840, 256]
    const float* __restrict__ bias,  // [256]
    float* __restrict__ C)           // [N, 256]
{
    __shared__ __align__(16) float As[BK][BM];   // transposed A tile
    __shared__ __align__(16) float Bs[BK][BN];

    const int tid  = threadIdx.x;
    const int row0 = blockIdx.x * BM;
    const int col0 = blockIdx.y * BN;
    const float* A = g_weighted;

    const int ty = tid >> 4;    // 0..15 (row octet)
    const int tx = tid & 15;    // 0..15 (col octet)

    const int arow = tid >> 1;         // 0..127
    const int ak4  = (tid & 1) * 4;    // 0 or 4
    const int brw  = tid >> 5;         // 0..7
    const int bc   = tid & 31;         // 0..31 (float4 column)

    float acc[8][8];
    #pragma unroll
    for (int i = 0; i < 8; i++)
        #pragma unroll
        for (int j = 0; j < 8; j++) acc[i][j] = 0.0f;

    const int grow = row0 + arow;
    const bool arow_ok = (grow < N_Q);

    for (int kb = 0; kb < BIGK; kb += BK) {
        float4 av = make_float4(0.f, 0.f, 0.f, 0.f);
        if (arow_ok)
            av = *reinterpret_cast<const float4*>(&A[(size_t)grow * BIGK + kb + ak4]);
        As[ak4 + 0][arow] = av.x;
        As[ak4 + 1][arow] = av.y;
        As[ak4 + 2][arow] = av.z;
        As[ak4 + 3][arow] = av.w;

        const float4 bv = *reinterpret_cast<const float4*>(
            &Bw[(size_t)(kb + brw) * COUT_ + col0 + bc * 4]);
        *reinterpret_cast<float4*>(&Bs[brw][bc * 4]) = bv;
        __syncthreads();

        #pragma unroll
        for (int k = 0; k < BK; k++) {
            float ra[8], rb[8];
            const float4 a0 = *reinterpret_cast<const float4*>(&As[k][ty * 8]);
            const float4 a1 = *reinterpret_cast<const float4*>(&As[k][ty * 8 + 4]);
            const float4 b0 = *reinterpret_cast<const float4*>(&Bs[k][tx * 8]);
            const float4 b1 = *reinterpret_cast<const float4*>(&Bs[k][tx * 8 + 4]);
            ra[0]=a0.x; ra[1]=a0.y; ra[2]=a0.z; ra[3]=a0.w;
            ra[4]=a1.x; ra[5]=a1.y; ra[6]=a1.z; ra[7]=a1.w;
            rb[0]=b0.x; rb[1]=b0.y; rb[2]=b0.z; rb[3]=b0.w;
            rb[4]=b1.x; rb[5]=b1.y; rb[6]=b1.z; rb[7]=b1.w;
            #pragma unroll
            for (int i = 0; i < 8; i++)
                #pragma unroll
                for (int j = 0; j < 8; j++)
                    acc[i][j] += ra[i] * rb[j];
        }
        __syncthreads();
    }

    // epilogue: bias + LeakyReLU(0.1)
    #pragma unroll
    for (int i = 0; i < 8; i++) {
        const int row = row0 + ty * 8 + i;
        if (row >= N_Q) continue;
        #pragma unroll
        for (int j4 = 0; j4 < 2; j4++) {
            const int col = col0 + tx * 8 + j4 * 4;
            float4 v;
            v.x = acc[i][j4 * 4 + 0] + bias[col + 0];
            v.y = acc[i][j4 * 4 + 1] + bias[col + 1];
            v.z = acc[i][j4 * 4 + 2] + bias[col + 2];
            v.w = acc[i][j4 * 4 + 3] + bias[col + 3];
            v.x = (v.x >= 0.f) ? v.x : 0.1f * v.x;
            v.y = (v.y >= 0.f) ? v.y : 0.1f * v.y;
            v.z = (v.z >= 0.f) ? v.z : 0.1f * v.z;
            v.w = (v.w >= 0.f) ? v.w : 0.1f * v.w;
            *reinterpret_cast<float4*>(&C[(size_t)row * COUT_ + col]) = v;
        }
    }
}

// ---------------------------------------------------------------------------
// Launch
// ---------------------------------------------------------------------------
extern "C" void kernel_launch(void* const* d_in, const int* in_sizes, int n_in,
                              void* d_out, int out_size) {
    const float* q_pts   = (const float*)d_in[0];
    const float* s_pts   = (const float*)d_in[1];
    const int*   inds    = (const int*)  d_in[2];
    const float* x       = (const float*)d_in[3];
    const float* q_lrf   = (const float*)d_in[4];
    const float* s_lrf   = (const float*)d_in[5];
    const float* kpts    = (const float*)d_in[6];
    const float* weights = (const float*)d_in[7];
    const float* W_lrf   = (const float*)d_in[8];
    const float* b_lrf   = (const float*)d_in[9];
    const float* bias    = (const float*)d_in[10];
    float* out = (float*)d_out;

    stage1_kernel<<<N_Q, 128>>>(q_pts, s_pts, inds, x, q_lrf, s_lrf,
                                kpts, W_lrf, b_lrf);

    dim3 grid((N_Q + BM - 1) / BM, COUT_ / BN);
    gemm_kernel<<<grid, 256>>>(weights, bias, out);
}

// round 3
// speedup vs baseline: 2.0002x; 2.0002x over previous
#include <cuda_runtime.h>
#include <cuda_bf16.h>
#include <cstdint>
#include <math.h>

// ---------------------------------------------------------------------------
// Problem constants
// ---------------------------------------------------------------------------
namespace {
constexpr int N_Q   = 20000;   // queries
constexpr int S_SUP = 20000;   // supports
constexpr int NEI   = 30;      // neighbors
constexpr int KP    = 15;      // kernel points
constexpr int CIN_  = 128;
constexpr int COUT_ = 256;
constexpr int BIGK  = KP * 256;     // 3840
constexpr float INV_EXT = 20.0f;    // 1 / 0.05

constexpr int M_PAD = 20096;        // 157 * 128

// GEMM tiling
constexpr int BM = 128, BN = 128, BK = 32;
constexpr int NKC = BIGK / BK;      // 120 k-chunks
constexpr int LDS_ = 40;            // smem row stride in bf16 (pad 32 -> 40)
constexpr int MAT_BYTES = 128 * LDS_ * 2;            // 10240 per matrix tile
constexpr int BUF_BYTES = 4 * MAT_BYTES;             // Ah|Al|Bh|Bl = 40960
constexpr int SMEM_DYN  = 2 * BUF_BYTES;             // 81920 (double buffer)
}

// ---------------------------------------------------------------------------
// Scratch (device globals; no runtime allocation allowed)
// pad rows [20000,20096) of A are never written -> stay zero (zero-init).
// ---------------------------------------------------------------------------
__device__ __nv_bfloat16 g_Ahi[(size_t)M_PAD * BIGK];
__device__ __nv_bfloat16 g_Alo[(size_t)M_PAD * BIGK];
__device__ __nv_bfloat16 g_Bhi[(size_t)COUT_ * BIGK];   // [n][k]
__device__ __nv_bfloat16 g_Blo[(size_t)COUT_ * BIGK];

// ---------------------------------------------------------------------------
// PTX helpers (portable: sm_80+ baseline, legal on family target)
// ---------------------------------------------------------------------------
__device__ __forceinline__ uint32_t smem_u32(const void* p) {
    uint32_t a;
    asm("{ .reg .u64 t; cvta.to.shared.u64 t, %1; cvt.u32.u64 %0, t; }"
        : "=r"(a) : "l"(p));
    return a;
}
__device__ __forceinline__ void cp16(uint32_t s, const void* g) {
    asm volatile("cp.async.cg.shared.global [%0], [%1], 16;"
                 :: "r"(s), "l"(g));
}
__device__ __forceinline__ void cp_commit() {
    asm volatile("cp.async.commit_group;");
}
__device__ __forceinline__ void cp_wait1() {
    asm volatile("cp.async.wait_group 1;" ::: "memory");
}
__device__ __forceinline__ void cp_wait0() {
    asm volatile("cp.async.wait_group 0;" ::: "memory");
}
__device__ __forceinline__ void ldmx4(uint32_t addr, uint32_t* r) {
    asm volatile("ldmatrix.sync.aligned.m8n8.x4.shared.b16 {%0,%1,%2,%3}, [%4];"
                 : "=r"(r[0]), "=r"(r[1]), "=r"(r[2]), "=r"(r[3]) : "r"(addr));
}
__device__ __forceinline__ void mma16816(float* c, const uint32_t* a,
                                         uint32_t b0, uint32_t b1) {
    asm volatile(
        "mma.sync.aligned.m16n8k16.row.col.f32.bf16.bf16.f32 "
        "{%0,%1,%2,%3}, {%4,%5,%6,%7}, {%8,%9}, {%0,%1,%2,%3};"
        : "+f"(c[0]), "+f"(c[1]), "+f"(c[2]), "+f"(c[3])
        : "r"(a[0]), "r"(a[1]), "r"(a[2]), "r"(a[3]), "r"(b0), "r"(b1));
}

// ---------------------------------------------------------------------------
// B split/transpose: weights [3840,256] fp32 -> Bhi/Blo [256][3840] bf16
// ---------------------------------------------------------------------------
__global__ __launch_bounds__(256) void bsplit_kernel(const float* __restrict__ W) {
    __shared__ float tile[32][33];
    const int bk0 = blockIdx.x * 32;
    const int c0  = blockIdx.y * 32;
    const int tx = threadIdx.x;    // 0..31
    const int ty = threadIdx.y;    // 0..7
    #pragma unroll
    for (int j = 0; j < 4; j++)
        tile[ty + 8 * j][tx] = W[(size_t)(bk0 + ty + 8 * j) * COUT_ + c0 + tx];
    __syncthreads();
    #pragma unroll
    for (int j = 0; j < 4; j++) {
        const float v = tile[tx][ty + 8 * j];
        const __nv_bfloat16 h = __float2bfloat16_rn(v);
        const __nv_bfloat16 l = __float2bfloat16_rn(v - __bfloat162float(h));
        const size_t off = (size_t)(c0 + ty + 8 * j) * BIGK + bk0 + tx;
        g_Bhi[off] = h;
        g_Blo[off] = l;
    }
}

// ---------------------------------------------------------------------------
// Stage 1: per-query geometry, LRF features, neighbor-weighted reduction.
// Writes A directly as bf16 hi/lo split. One block per query, 128 threads.
// ---------------------------------------------------------------------------
__global__ __launch_bounds__(128) void stage1_kernel(
    const float* __restrict__ q_pts,
    const float* __restrict__ s_pts,
    const int*   __restrict__ neighb_inds,
    const float* __restrict__ x,
    const float* __restrict__ q_lrf,
    const float* __restrict__ s_lrf,
    const float* __restrict__ kpts,
    const float* __restrict__ W_lrf,
    const float* __restrict__ b_lrf)
{
    __shared__ __align__(16) float ql[36];
    __shared__ __align__(16) float kp_s[48];
    __shared__ __align__(16) float Wl[36 * 32];
    __shared__ __align__(16) float bl[32];
    __shared__ __align__(16) float w_sm[16 * 120];
    __shared__ __align__(16) float f_sm[30 * 272];
    __shared__ int   ind_s[30];
    __shared__ float qp[3];

    const int n   = blockIdx.x;
    const int tid = threadIdx.x;

    if (tid < 36) ql[tid]    = q_lrf[(size_t)n * 36 + tid];
    if (tid < 45) kp_s[tid]  = kpts[tid];
    if (tid < 3)  qp[tid]    = q_pts[(size_t)n * 3 + tid];
    if (tid < 32) bl[tid]    = b_lrf[tid];
    if (tid < 30) ind_s[tid] = neighb_inds[(size_t)n * NEI + tid];
    for (int i = tid; i < 36 * 32; i += 128) Wl[i] = W_lrf[i];
    if (tid < 120) w_sm[15 * 120 + tid] = 0.0f;
    __syncthreads();

    #pragma unroll 1
    for (int i = tid; i < NEI * CIN_; i += 128) {
        const int m  = i >> 7;
        const int qc = i & 127;
        const int ind = ind_s[m];
        float v = 0.0f;
        if (ind < S_SUP) v = x[(size_t)ind * CIN_ + qc];
        f_sm[m * 272 + (qc >> 5) * 68 + (qc & 31)] = v;
    }

    if (tid < 120) {
        const int m = tid >> 2;
        const int q = tid & 3;
        const int ind = ind_s[m];
        const bool valid = (ind < S_SUP);
        const int indc = valid ? ind : 0;
        const float* qlr = &ql[q * 9];

        const float nb0 = s_pts[(size_t)indc * 3 + 0] - qp[0];
        const float nb1 = s_pts[(size_t)indc * 3 + 1] - qp[1];
        const float nb2 = s_pts[(size_t)indc * 3 + 2] - qp[2];
        const float a0 = nb0 * qlr[0] + nb1 * qlr[3] + nb2 * qlr[6];
        const float a1 = nb0 * qlr[1] + nb1 * qlr[4] + nb2 * qlr[7];
        const float a2 = nb0 * qlr[2] + nb1 * qlr[5] + nb2 * qlr[8];

        #pragma unroll
        for (int k = 0; k < KP; k++) {
            const float d0 = a0 - kp_s[k * 3 + 0];
            const float d1 = a1 - kp_s[k * 3 + 1];
            const float d2 = a2 - kp_s[k * 3 + 2];
            float w = 1.0f - sqrtf(d0 * d0 + d1 * d1 + d2 * d2) * INV_EXT;
            w = fmaxf(w, 0.0f);
            w_sm[k * 120 + m * 4 + q] = valid ? w : 0.0f;
        }

        float sl[36];
        {
            const float4* p = reinterpret_cast<const float4*>(s_lrf + (size_t)indc * 36);
            #pragma unroll
            for (int t = 0; t < 9; t++) {
                const float4 v = p[t];
                sl[t * 4 + 0] = v.x; sl[t * 4 + 1] = v.y;
                sl[t * 4 + 2] = v.z; sl[t * 4 + 3] = v.w;
            }
        }
        float al[36];
        #pragma unroll
        for (int s = 0; s < 4; s++)
            #pragma unroll
            for (int i = 0; i < 3; i++)
                #pragma unroll
                for (int j = 0; j < 3; j++) {
                    al[s * 9 + i * 3 + j] =
                        qlr[0 * 3 + i] * sl[s * 9 + 0 * 3 + j] +
                        qlr[1 * 3 + i] * sl[s * 9 + 1 * 3 + j] +
                        qlr[2 * 3 + i] * sl[s * 9 + 2 * 3 + j];
                }
        float4 lf[8];
        #pragma unroll
        for (int c4 = 0; c4 < 8; c4++) {
            lf[c4].x = bl[c4 * 4 + 0]; lf[c4].y = bl[c4 * 4 + 1];
            lf[c4].z = bl[c4 * 4 + 2]; lf[c4].w = bl[c4 * 4 + 3];
        }
        #pragma unroll
        for (int t = 0; t < 36; t++) {
            const float a = al[t];
            const float4* wr = reinterpret_cast<const float4*>(&Wl[t * 32]);
            #pragma unroll
            for (int c4 = 0; c4 < 8; c4++) {
                const float4 wv = wr[c4];
                lf[c4].x += a * wv.x; lf[c4].y += a * wv.y;
                lf[c4].z += a * wv.z; lf[c4].w += a * wv.w;
            }
        }
        if (!valid) {
            #pragma unroll
            for (int c4 = 0; c4 < 8; c4++) lf[c4] = make_float4(0.f, 0.f, 0.f, 0.f);
        }
        float4* frow = reinterpret_cast<float4*>(&f_sm[m * 272 + q * 68 + 32]);
        #pragma unroll
        for (int c4 = 0; c4 < 8; c4++) frow[c4] = lf[c4];
    }
    __syncthreads();

    // phase 2: weighted[q][k][c] = sum_m w[q][k][m] * f[m][q][c]
    const int half = tid >> 6;
    const int q2   = (tid >> 4) & 3;
    const int c4   = tid & 15;
    const int k0   = half * 8;

    float4 acc[8];
    #pragma unroll
    for (int i = 0; i < 8; i++) acc[i] = make_float4(0.f, 0.f, 0.f, 0.f);

    #pragma unroll 1
    for (int m = 0; m < NEI; m++) {
        const float4 f4 = *reinterpret_cast<const float4*>(&f_sm[m * 272 + q2 * 68 + c4 * 4]);
        const float* wp = &w_sm[k0 * 120 + m * 4 + q2];
        #pragma unroll
        for (int kl = 0; kl < 8; kl++) {
            const float wv = wp[kl * 120];
            acc[kl].x += wv * f4.x; acc[kl].y += wv * f4.y;
            acc[kl].z += wv * f4.z; acc[kl].w += wv * f4.w;
        }
    }

    #pragma unroll
    for (int kl = 0; kl < 8; kl++) {
        const int k = k0 + kl;
        if (k < KP) {
            const size_t off = (size_t)n * BIGK + k * 256 + q2 * 64 + c4 * 4;
            const float vv[4] = {acc[kl].x, acc[kl].y, acc[kl].z, acc[kl].w};
            ushort4 h4, l4;
            unsigned short* hp = &h4.x;
            unsigned short* lp = &l4.x;
            #pragma unroll
            for (int e = 0; e < 4; e++) {
                const __nv_bfloat16 h = __float2bfloat16_rn(vv[e]);
                const __nv_bfloat16 l = __float2bfloat16_rn(vv[e] - __bfloat162float(h));
                hp[e] = __bfloat16_as_ushort(h);
                lp[e] = __bfloat16_as_ushort(l);
            }
            *reinterpret_cast<ushort4*>(&g_Ahi[off]) = h4;
            *reinterpret_cast<ushort4*>(&g_Alo[off]) = l4;
        }
    }
}

// ---------------------------------------------------------------------------
// Stage 2: mma.sync bf16 GEMM.  out = (Ah+Al)@(Bh+Bl)^T ~= AhBh + AhBl + AlBh
// CTA: 128x128, BK=32, 8 warps (warp tile 64x32), cp.async double buffer.
// ---------------------------------------------------------------------------
__global__ __launch_bounds__(256)
void gemm_mma_kernel(const float* __restrict__ bias, float* __restrict__ C)
{
    extern __shared__ __align__(16) char sm[];
    const uint32_t s0 = smem_u32(sm);

    const int tid  = threadIdx.x;
    const int wid  = tid >> 5;
    const int lane = tid & 31;
    const int r0   = blockIdx.x * BM;
    const int c0   = blockIdx.y * BN;

    const int wm = (wid & 1) * 64;   // warp row offset
    const int wn = (wid >> 1) * 32;  // warp col offset

    float acc[4][4][4];
    #pragma unroll
    for (int i = 0; i < 4; i++)
        #pragma unroll
        for (int j = 0; j < 4; j++)
            #pragma unroll
            for (int e = 0; e < 4; e++) acc[i][j][e] = 0.0f;

    // ---- chunk loader (cp.async): Ah|Al|Bh|Bl tiles, 128x32 each ----
    auto load_chunk = [&](int c, int buf) {
        const int kc = c * BK;
        const uint32_t base = s0 + buf * BUF_BYTES;
        #pragma unroll
        for (int it = 0; it < 2; it++) {
            const int i   = tid + it * 256;          // 0..511
            const int row = i >> 2;
            const int kq  = (i & 3) * 8;
            const uint32_t so = row * (LDS_ * 2) + kq * 2;
            const size_t ga = (size_t)(r0 + row) * BIGK + kc + kq;
            const size_t gb = (size_t)(c0 + row) * BIGK + kc + kq;
            cp16(base + 0 * MAT_BYTES + so, &g_Ahi[ga]);
            cp16(base + 1 * MAT_BYTES + so, &g_Alo[ga]);
            cp16(base + 2 * MAT_BYTES + so, &g_Bhi[gb]);
            cp16(base + 3 * MAT_BYTES + so, &g_Blo[gb]);
        }
        cp_commit();
    };

    // ldmatrix lane addressing (element offsets within a tile)
    const int a_row = lane & 15;             // row within 16
    const int a_kof = (lane >> 4) * 8;       // 0 or 8
    const int b_nof = ((lane >> 4) * 8) + (lane & 7);   // n within 16
    const int b_kof = ((lane >> 3) & 1) * 8;            // 0 or 8

    load_chunk(0, 0);

    for (int c = 0; c < NKC; c++) {
        const int buf = c & 1;
        if (c + 1 < NKC) { load_chunk(c + 1, buf ^ 1); cp_wait1(); }
        else             { cp_wait0(); }
        __syncthreads();

        const uint32_t bA  = s0 + buf * BUF_BYTES;
        const uint32_t bAl = bA + MAT_BYTES;
        const uint32_t bB  = bA + 2 * MAT_BYTES;
        const uint32_t bBl = bA + 3 * MAT_BYTES;

        #pragma unroll
        for (int ks = 0; ks < 2; ks++) {
            const int k16 = ks * 16;
            uint32_t aH[4][4], aL[4][4], bH[4][2], bL[4][2];

            #pragma unroll
            for (int mt = 0; mt < 4; mt++) {
                const uint32_t off =
                    (wm + mt * 16 + a_row) * (LDS_ * 2) + (k16 + a_kof) * 2;
                ldmx4(bA  + off, aH[mt]);
                ldmx4(bAl + off, aL[mt]);
            }
            #pragma unroll
            for (int np = 0; np < 2; np++) {
                const uint32_t off =
                    (wn + np * 16 + b_nof) * (LDS_ * 2) + (k16 + b_kof) * 2;
                uint32_t t[4];
                ldmx4(bB + off, t);
                bH[np * 2 + 0][0] = t[0]; bH[np * 2 + 0][1] = t[1];
                bH[np * 2 + 1][0] = t[2]; bH[np * 2 + 1][1] = t[3];
                ldmx4(bBl + off, t);
                bL[np * 2 + 0][0] = t[0]; bL[np * 2 + 0][1] = t[1];
                bL[np * 2 + 1][0] = t[2]; bL[np * 2 + 1][1] = t[3];
            }

            #pragma unroll
            for (int mt = 0; mt < 4; mt++)
                #pragma unroll
                for (int nt = 0; nt < 4; nt++) {
                    mma16816(acc[mt][nt], aH[mt], bH[nt][0], bH[nt][1]);
                    mma16816(acc[mt][nt], aH[mt], bL[nt][0], bL[nt][1]);
                    mma16816(acc[mt][nt], aL[mt], bH[nt][0], bH[nt][1]);
                }
        }
        __syncthreads();
    }

    // ---- epilogue: bias + LeakyReLU, direct stores (float2) ----
    const int erow = lane >> 2;          // 0..7
    const int ecol = (lane & 3) * 2;
    #pragma unroll
    for (int nt = 0; nt < 4; nt++) {
        const int col = c0 + wn + nt * 8 + ecol;
        const float b0 = bias[col], b1 = bias[col + 1];
        #pragma unroll
        for (int mt = 0; mt < 4; mt++) {
            #pragma unroll
            for (int h = 0; h < 2; h++) {
                const int row = r0 + wm + mt * 16 + erow + h * 8;
                if (row < N_Q) {
                    float v0 = acc[mt][nt][h * 2 + 0] + b0;
                    float v1 = acc[mt][nt][h * 2 + 1] + b1;
                    v0 = (v0 >= 0.f) ? v0 : 0.1f * v0;
                    v1 = (v1 >= 0.f) ? v1 : 0.1f * v1;
                    *reinterpret_cast<float2*>(&C[(size_t)row * COUT_ + col]) =
                        make_float2(v0, v1);
                }
            }
        }
    }
}

// ---------------------------------------------------------------------------
// Launch
// ---------------------------------------------------------------------------
extern "C" void kernel_launch(void* const* d_in, const int* in_sizes, int n_in,
                              void* d_out, int out_size) {
    const float* q_pts   = (const float*)d_in[0];
    const float* s_pts   = (const float*)d_in[1];
    const int*   inds    = (const int*)  d_in[2];
    const float* x       = (const float*)d_in[3];
    const float* q_lrf   = (const float*)d_in[4];
    const float* s_lrf   = (const float*)d_in[5];
    const float* kpts    = (const float*)d_in[6];
    const float* weights = (const float*)d_in[7];
    const float* W_lrf   = (const float*)d_in[8];
    const float* b_lrf   = (const float*)d_in[9];
    const float* bias    = (const float*)d_in[10];
    float* out = (float*)d_out;

    cudaFuncSetAttribute(gemm_mma_kernel,
                         cudaFuncAttributeMaxDynamicSharedMemorySize, SMEM_DYN);

    dim3 bgrid(BIGK / 32, COUT_ / 32);
    bsplit_kernel<<<bgrid, dim3(32, 8)>>>(weights);

    stage1_kernel<<<N_Q, 128>>>(q_pts, s_pts, inds, x, q_lrf, s_lrf,
                                kpts, W_lrf, b_lrf);

    dim3 ggrid(M_PAD / BM, COUT_ / BN);
    gemm_mma_kernel<<<ggrid, 256, SMEM_DYN>>>(bias, out);
}

// round 4
// speedup vs baseline: 2.1877x; 1.0937x over previous
#include <cuda_runtime.h>
#include <cuda_bf16.h>
#include <cstdint>
#include <math.h>

// ---------------------------------------------------------------------------
// Problem constants
// ---------------------------------------------------------------------------
namespace {
constexpr int N_Q   = 20000;   // queries
constexpr int S_SUP = 20000;   // supports
constexpr int NEI   = 30;      // neighbors
constexpr int KP    = 15;      // kernel points
constexpr int CIN_  = 128;
constexpr int COUT_ = 256;
constexpr float INV_EXT = 20.0f;    // 1 / 0.05

constexpr int M_PAD = 20096;        // 157 * 128

// Extended-K layout: per k (15): 4 q-groups of 72 slots
//   j in [0,32): x part;  j in [32,68): 36 al channels (H);  j=68: validity
//   (b_lrf folded into B via validity channel);  j in [69,72): zero pad
constexpr int QW    = 72;                 // slots per (q)
constexpr int KROW  = 4 * QW;             // 288 slots per k
constexpr int BIGK2 = KP * KROW;          // 4320

// GEMM tiling
constexpr int BM = 128, BN = 128, BK = 32;
constexpr int NKC = BIGK2 / BK;           // 135
constexpr int LDS_ = 40;                  // smem row stride in bf16
constexpr int MAT_BYTES = 128 * LDS_ * 2; // 10240 per matrix tile
constexpr int BUF_BYTES = 4 * MAT_BYTES;  // Ah|Al|Bh|Bl = 40960
constexpr int SMEM_DYN  = 2 * BUF_BYTES;  // 81920 (double buffer)
}

// ---------------------------------------------------------------------------
// Scratch (device globals). Zero-initialized; pad rows/slots never written.
// ---------------------------------------------------------------------------
__device__ __nv_bfloat16 g_Ahi[(size_t)M_PAD * BIGK2];
__device__ __nv_bfloat16 g_Alo[(size_t)M_PAD * BIGK2];
__device__ __nv_bfloat16 g_Bhi[(size_t)COUT_ * BIGK2];   // [co][kidx]
__device__ __nv_bfloat16 g_Blo[(size_t)COUT_ * BIGK2];

// ---------------------------------------------------------------------------
// PTX helpers (sm_80+ baseline; legal on family target)
// ---------------------------------------------------------------------------
__device__ __forceinline__ uint32_t smem_u32(const void* p) {
    uint32_t a;
    asm("{ .reg .u64 t; cvta.to.shared.u64 t, %1; cvt.u32.u64 %0, t; }"
        : "=r"(a) : "l"(p));
    return a;
}
__device__ __forceinline__ void cp16(uint32_t s, const void* g) {
    asm volatile("cp.async.cg.shared.global [%0], [%1], 16;" :: "r"(s), "l"(g));
}
__device__ __forceinline__ void cp_commit() {
    asm volatile("cp.async.commit_group;");
}
__device__ __forceinline__ void cp_wait1() {
    asm volatile("cp.async.wait_group 1;" ::: "memory");
}
__device__ __forceinline__ void cp_wait0() {
    asm volatile("cp.async.wait_group 0;" ::: "memory");
}
__device__ __forceinline__ void ldmx4(uint32_t addr, uint32_t* r) {
    asm volatile("ldmatrix.sync.aligned.m8n8.x4.shared.b16 {%0,%1,%2,%3}, [%4];"
                 : "=r"(r[0]), "=r"(r[1]), "=r"(r[2]), "=r"(r[3]) : "r"(addr));
}
__device__ __forceinline__ void mma16816(float* c, const uint32_t* a,
                                         uint32_t b0, uint32_t b1) {
    asm volatile(
        "mma.sync.aligned.m16n8k16.row.col.f32.bf16.bf16.f32 "
        "{%0,%1,%2,%3}, {%4,%5,%6,%7}, {%8,%9}, {%0,%1,%2,%3};"
        : "+f"(c[0]), "+f"(c[1]), "+f"(c[2]), "+f"(c[3])
        : "r"(a[0]), "r"(a[1]), "r"(a[2]), "r"(a[3]), "r"(b0), "r"(b1));
}
__device__ __forceinline__ void store_split(size_t idx, float v,
                                            __nv_bfloat16* hi, __nv_bfloat16* lo) {
    const __nv_bfloat16 h = __float2bfloat16_rn(v);
    const __nv_bfloat16 l = __float2bfloat16_rn(v - __bfloat162float(h));
    hi[idx] = h; lo[idx] = l;
}

// ---------------------------------------------------------------------------
// B prep: build g_Bhi/g_Blo [256][4320] from weights, W_lrf, b_lrf.
// Block (k, q), 256 threads = co.
//   j<32:   weights[k][q*64+j][co]
//   j=32+t: W2 = sum_c W_lrf[t][c]*weights[k][q*64+32+c][co]   (t<36)
//   j=68:   W3 = sum_c b_lrf[c]*weights[k][q*64+32+c][co]
//   j>68:   0
// ---------------------------------------------------------------------------
__global__ __launch_bounds__(256) void bprep_kernel(
    const float* __restrict__ W,       // [15][256][256]
    const float* __restrict__ W_lrf,   // [36][32]
    const float* __restrict__ b_lrf)   // [32]
{
    __shared__ float Wl[36 * 32];
    __shared__ float bl[32];
    const int k  = blockIdx.x;
    const int q  = blockIdx.y;
    const int co = threadIdx.x;

    for (int i = co; i < 36 * 32; i += 256) Wl[i] = W_lrf[i];
    if (co < 32) bl[co] = b_lrf[co];
    __syncthreads();

    float acc[37];
    #pragma unroll
    for (int t = 0; t < 37; t++) acc[t] = 0.0f;

    const float* Wb = W + ((size_t)k * 256 + q * 64) * 256;
    #pragma unroll 4
    for (int c = 0; c < 32; c++) {
        const float wv = Wb[(size_t)(32 + c) * 256 + co];
        #pragma unroll
        for (int t = 0; t < 36; t++) acc[t] += Wl[t * 32 + c] * wv;
        acc[36] += bl[c] * wv;
    }

    const size_t rb = (size_t)co * BIGK2 + k * KROW + q * QW;
    #pragma unroll 4
    for (int j = 0; j < 32; j++)
        store_split(rb + j, Wb[(size_t)j * 256 + co], g_Bhi, g_Blo);
    #pragma unroll
    for (int t = 0; t < 37; t++)
        store_split(rb + 32 + t, acc[t], g_Bhi, g_Blo);
    #pragma unroll
    for (int j = 69; j < 72; j++)
        store_split(rb + j, 0.0f, g_Bhi, g_Blo);
}

// ---------------------------------------------------------------------------
// Stage 1: per-query geometry + neighbor reduction (x part and H part).
// One block per query, 128 threads.
// ---------------------------------------------------------------------------
__global__ __launch_bounds__(128) void stage1_kernel(
    const float* __restrict__ q_pts,
    const float* __restrict__ s_pts,
    const int*   __restrict__ neighb_inds,
    const float* __restrict__ x,
    const float* __restrict__ q_lrf,
    const float* __restrict__ s_lrf,
    const float* __restrict__ kpts)
{
    __shared__ __align__(16) float ql[36];
    __shared__ __align__(16) float kp_s[48];
    __shared__ __align__(16) float w_sm[16 * 120];   // [k][m*4+q], k=15 pad row
    __shared__ __align__(16) float f_sm[30 * KROW];  // [m][q*72 + j]
    __shared__ int   ind_s[30];
    __shared__ float qp[3];

    const int n   = blockIdx.x;
    const int tid = threadIdx.x;

    if (tid < 36) ql[tid]    = q_lrf[(size_t)n * 36 + tid];
    if (tid < 45) kp_s[tid]  = kpts[tid];
    if (tid < 3)  qp[tid]    = q_pts[(size_t)n * 3 + tid];
    if (tid < 30) ind_s[tid] = neighb_inds[(size_t)n * NEI + tid];
    if (tid < 120) w_sm[15 * 120 + tid] = 0.0f;      // pad k-row
    __syncthreads();

    // ---- x gather into j<32 slots (coalesced over channels) ----
    #pragma unroll 1
    for (int i = tid; i < NEI * CIN_; i += 128) {
        const int m  = i >> 7;
        const int qc = i & 127;
        const int ind = ind_s[m];
        float v = 0.0f;
        if (ind < S_SUP) v = x[(size_t)ind * CIN_ + qc];
        f_sm[m * KROW + (qc >> 5) * QW + (qc & 31)] = v;
    }

    // ---- per-(m,q) geometry: KP weights + aligned LRF channels ----
    if (tid < 120) {
        const int m = tid >> 2;
        const int q = tid & 3;
        const int ind = ind_s[m];
        const bool valid = (ind < S_SUP);
        const int indc = valid ? ind : 0;
        const float* qlr = &ql[q * 9];

        const float nb0 = s_pts[(size_t)indc * 3 + 0] - qp[0];
        const float nb1 = s_pts[(size_t)indc * 3 + 1] - qp[1];
        const float nb2 = s_pts[(size_t)indc * 3 + 2] - qp[2];
        const float a0 = nb0 * qlr[0] + nb1 * qlr[3] + nb2 * qlr[6];
        const float a1 = nb0 * qlr[1] + nb1 * qlr[4] + nb2 * qlr[7];
        const float a2 = nb0 * qlr[2] + nb1 * qlr[5] + nb2 * qlr[8];

        #pragma unroll
        for (int k = 0; k < KP; k++) {
            const float d0 = a0 - kp_s[k * 3 + 0];
            const float d1 = a1 - kp_s[k * 3 + 1];
            const float d2 = a2 - kp_s[k * 3 + 2];
            float w = 1.0f - sqrtf(d0 * d0 + d1 * d1 + d2 * d2) * INV_EXT;
            w = fmaxf(w, 0.0f);
            w_sm[k * 120 + m * 4 + q] = valid ? w : 0.0f;
        }

        // support LRF row
        float sl[36];
        {
            const float4* p = reinterpret_cast<const float4*>(s_lrf + (size_t)indc * 36);
            #pragma unroll
            for (int t = 0; t < 9; t++) {
                const float4 v = p[t];
                sl[t * 4 + 0] = v.x; sl[t * 4 + 1] = v.y;
                sl[t * 4 + 2] = v.z; sl[t * 4 + 3] = v.w;
            }
        }
        // al[s,i,j] = sum_kk ql[q,kk,i]*sl[s,kk,j]  -> channels j=32..67
        float* fr = &f_sm[m * KROW + q * QW];
        #pragma unroll
        for (int s = 0; s < 4; s++)
            #pragma unroll
            for (int i = 0; i < 3; i++)
                #pragma unroll
                for (int j = 0; j < 3; j++) {
                    fr[32 + s * 9 + i * 3 + j] =
                        qlr[0 * 3 + i] * sl[s * 9 + 0 * 3 + j] +
                        qlr[1 * 3 + i] * sl[s * 9 + 1 * 3 + j] +
                        qlr[2 * 3 + i] * sl[s * 9 + 2 * 3 + j];
                }
        fr[68] = valid ? 1.0f : 0.0f;   // validity channel (b_lrf term)
        fr[69] = 0.0f; fr[70] = 0.0f; fr[71] = 0.0f;
    }
    __syncthreads();

    // ---- phase 2: A[q,k,j] = sum_m w[q,k,m] * f[m,q,j] ----
    // 144 tasks: (h in 2) x (q in 4) x (c17 in 18); each does 8 k x float4.
    #pragma unroll 1
    for (int pass = 0; pass < 2; pass++) {
        const int t = tid + pass * 128;
        if (t >= 144) break;
        const int c17 = t % 18;
        const int rem = t / 18;
        const int q2  = rem & 3;
        const int h   = rem >> 2;
        const int k0  = h * 8;

        float4 acc[8];
        #pragma unroll
        for (int i = 0; i < 8; i++) acc[i] = make_float4(0.f, 0.f, 0.f, 0.f);

        #pragma unroll 1
        for (int m = 0; m < NEI; m++) {
            const float4 f4 = *reinterpret_cast<const float4*>(
                &f_sm[m * KROW + q2 * QW + c17 * 4]);
            const float* wp = &w_sm[k0 * 120 + m * 4 + q2];
            #pragma unroll
            for (int kl = 0; kl < 8; kl++) {
                const float wv = wp[kl * 120];
                acc[kl].x += wv * f4.x; acc[kl].y += wv * f4.y;
                acc[kl].z += wv * f4.z; acc[kl].w += wv * f4.w;
            }
        }

        #pragma unroll
        for (int kl = 0; kl < 8; kl++) {
            const int k = k0 + kl;
            if (k < KP) {
                const size_t off = (size_t)n * BIGK2 + k * KROW + q2 * QW + c17 * 4;
                const float vv[4] = {acc[kl].x, acc[kl].y, acc[kl].z, acc[kl].w};
                ushort4 h4, l4;
                unsigned short* hp = &h4.x;
                unsigned short* lp = &l4.x;
                #pragma unroll
                for (int e = 0; e < 4; e++) {
                    const __nv_bfloat16 hh = __float2bfloat16_rn(vv[e]);
                    const __nv_bfloat16 ll = __float2bfloat16_rn(vv[e] - __bfloat162float(hh));
                    hp[e] = __bfloat16_as_ushort(hh);
                    lp[e] = __bfloat16_as_ushort(ll);
                }
                *reinterpret_cast<ushort4*>(&g_Ahi[off]) = h4;
                *reinterpret_cast<ushort4*>(&g_Alo[off]) = l4;
            }
        }
    }
}

// ---------------------------------------------------------------------------
// Stage 2: mma.sync bf16 GEMM. out = (Ah+Al)@(Bh+Bl)^T ~= AhBh + AhBl + AlBh
// CTA 128x128, BK=32, 4 warps (warp tile 64x64), cp.async double buffer.
// ---------------------------------------------------------------------------
__global__ __launch_bounds__(128)
void gemm_mma_kernel(const float* __restrict__ bias, float* __restrict__ C)
{
    extern __shared__ __align__(16) char sm[];
    const uint32_t s0 = smem_u32(sm);

    const int tid  = threadIdx.x;
    const int wid  = tid >> 5;
    const int lane = tid & 31;
    const int r0   = blockIdx.x * BM;
    const int c0   = blockIdx.y * BN;

    const int wm = (wid & 1) * 64;
    const int wn = (wid >> 1) * 64;

    float acc[4][8][4];
    #pragma unroll
    for (int i = 0; i < 4; i++)
        #pragma unroll
        for (int j = 0; j < 8; j++)
            #pragma unroll
            for (int e = 0; e < 4; e++) acc[i][j][e] = 0.0f;

    auto load_chunk = [&](int c, int buf) {
        const int kc = c * BK;
        const uint32_t base = s0 + buf * BUF_BYTES;
        #pragma unroll
        for (int it = 0; it < 4; it++) {
            const int i   = tid + it * 128;          // 0..511
            const int row = i >> 2;
            const int kq  = (i & 3) * 8;
            const uint32_t so = row * (LDS_ * 2) + kq * 2;
            const size_t ga = (size_t)(r0 + row) * BIGK2 + kc + kq;
            const size_t gb = (size_t)(c0 + row) * BIGK2 + kc + kq;
            cp16(base + 0 * MAT_BYTES + so, &g_Ahi[ga]);
            cp16(base + 1 * MAT_BYTES + so, &g_Alo[ga]);
            cp16(base + 2 * MAT_BYTES + so, &g_Bhi[gb]);
            cp16(base + 3 * MAT_BYTES + so, &g_Blo[gb]);
        }
        cp_commit();
    };

    const int a_row = lane & 15;
    const int a_kof = (lane >> 4) * 8;
    const int b_nof = ((lane >> 4) * 8) + (lane & 7);
    const int b_kof = ((lane >> 3) & 1) * 8;

    load_chunk(0, 0);

    for (int c = 0; c < NKC; c++) {
        const int buf = c & 1;
        if (c + 1 < NKC) { load_chunk(c + 1, buf ^ 1); cp_wait1(); }
        else             { cp_wait0(); }
        __syncthreads();

        const uint32_t bA  = s0 + buf * BUF_BYTES;
        const uint32_t bAl = bA + MAT_BYTES;
        const uint32_t bB  = bA + 2 * MAT_BYTES;
        const uint32_t bBl = bA + 3 * MAT_BYTES;

        #pragma unroll
        for (int ks = 0; ks < 2; ks++) {
            const int k16 = ks * 16;
            uint32_t aH[4][4], aL[4][4], bH[8][2], bL[8][2];

            #pragma unroll
            for (int mt = 0; mt < 4; mt++) {
                const uint32_t off =
                    (wm + mt * 16 + a_row) * (LDS_ * 2) + (k16 + a_kof) * 2;
                ldmx4(bA  + off, aH[mt]);
                ldmx4(bAl + off, aL[mt]);
            }
            #pragma unroll
            for (int np = 0; np < 4; np++) {
                const uint32_t off =
                    (wn + np * 16 + b_nof) * (LDS_ * 2) + (k16 + b_kof) * 2;
                uint32_t t[4];
                ldmx4(bB + off, t);
                bH[np * 2 + 0][0] = t[0]; bH[np * 2 + 0][1] = t[1];
                bH[np * 2 + 1][0] = t[2]; bH[np * 2 + 1][1] = t[3];
                ldmx4(bBl + off, t);
                bL[np * 2 + 0][0] = t[0]; bL[np * 2 + 0][1] = t[1];
                bL[np * 2 + 1][0] = t[2]; bL[np * 2 + 1][1] = t[3];
            }

            #pragma unroll
            for (int mt = 0; mt < 4; mt++)
                #pragma unroll
                for (int nt = 0; nt < 8; nt++) {
                    mma16816(acc[mt][nt], aH[mt], bH[nt][0], bH[nt][1]);
                    mma16816(acc[mt][nt], aH[mt], bL[nt][0], bL[nt][1]);
                    mma16816(acc[mt][nt], aL[mt], bH[nt][0], bH[nt][1]);
                }
        }
        __syncthreads();
    }

    // epilogue: bias + LeakyReLU
    const int erow = lane >> 2;
    const int ecol = (lane & 3) * 2;
    #pragma unroll
    for (int nt = 0; nt < 8; nt++) {
        const int col = c0 + wn + nt * 8 + ecol;
        const float b0 = bias[col], b1 = bias[col + 1];
        #pragma unroll
        for (int mt = 0; mt < 4; mt++) {
            #pragma unroll
            for (int h = 0; h < 2; h++) {
                const int row = r0 + wm + mt * 16 + erow + h * 8;
                if (row < N_Q) {
                    float v0 = acc[mt][nt][h * 2 + 0] + b0;
                    float v1 = acc[mt][nt][h * 2 + 1] + b1;
                    v0 = (v0 >= 0.f) ? v0 : 0.1f * v0;
                    v1 = (v1 >= 0.f) ? v1 : 0.1f * v1;
                    *reinterpret_cast<float2*>(&C[(size_t)row * COUT_ + col]) =
                        make_float2(v0, v1);
                }
            }
        }
    }
}

// ---------------------------------------------------------------------------
// Launch
// ---------------------------------------------------------------------------
extern "C" void kernel_launch(void* const* d_in, const int* in_sizes, int n_in,
                              void* d_out, int out_size) {
    const float* q_pts   = (const float*)d_in[0];
    const float* s_pts   = (const float*)d_in[1];
    const int*   inds    = (const int*)  d_in[2];
    const float* x       = (const float*)d_in[3];
    const float* q_lrf   = (const float*)d_in[4];
    const float* s_lrf   = (const float*)d_in[5];
    const float* kpts    = (const float*)d_in[6];
    const float* weights = (const float*)d_in[7];
    const float* W_lrf   = (const float*)d_in[8];
    const float* b_lrf   = (const float*)d_in[9];
    const float* bias    = (const float*)d_in[10];
    float* out = (float*)d_out;

    cudaFuncSetAttribute(gemm_mma_kernel,
                         cudaFuncAttributeMaxDynamicSharedMemorySize, SMEM_DYN);

    bprep_kernel<<<dim3(KP, 4), 256>>>(weights, W_lrf, b_lrf);

    stage1_kernel<<<N_Q, 128>>>(q_pts, s_pts, inds, x, q_lrf, s_lrf, kpts);

    dim3 ggrid(M_PAD / BM, COUT_ / BN);
    gemm_mma_kernel<<<ggrid, 128, SMEM_DYN>>>(bias, out);
}

// round 5
// speedup vs baseline: 3.9909x; 1.8242x over previous
#include <cuda_runtime.h>
#include <cuda_fp16.h>
#include <cstdint>
#include <math.h>

// ---------------------------------------------------------------------------
// Problem constants
// ---------------------------------------------------------------------------
namespace {
constexpr int N_Q   = 20000;
constexpr int S_SUP = 20000;
constexpr int NEI   = 30;
constexpr int KP    = 15;
constexpr int CIN_  = 128;
constexpr int COUT_ = 256;
constexpr float INV_EXT = 20.0f;

constexpr int M_PAD = 20096;        // 157*128

// Extended-K layout: per k: 4 q-groups of 72 slots
//   j<32: x part; j in [32,68): 36 al channels; j=68: validity; j>68: pad
constexpr int QW    = 72;
constexpr int KROW  = 4 * QW;             // 288
constexpr int BIGK2 = KP * KROW;          // 4320

// GEMM tiling
constexpr int BM = 128, BN = 128, BK = 32;
constexpr int NKC = BIGK2 / BK;           // 135
constexpr int LDS_ = 40;                  // smem row stride (fp16 elems)
constexpr int MAT_BYTES = 128 * LDS_ * 2; // 10240
constexpr int BUF_BYTES = 2 * MAT_BYTES;  // A|B = 20480
constexpr int SMEM_DYN  = 2 * BUF_BYTES;  // 40960 double-buffered
}

// ---------------------------------------------------------------------------
// Scratch (device globals, zero-initialized; pad rows never written)
// ---------------------------------------------------------------------------
__device__ __half g_A[(size_t)M_PAD * BIGK2];
__device__ __half g_B[(size_t)COUT_ * BIGK2];   // [co][kidx]

// ---------------------------------------------------------------------------
// PTX helpers (sm_80+ baseline; legal on family target)
// ---------------------------------------------------------------------------
__device__ __forceinline__ uint32_t smem_u32(const void* p) {
    uint32_t a;
    asm("{ .reg .u64 t; cvta.to.shared.u64 t, %1; cvt.u32.u64 %0, t; }"
        : "=r"(a) : "l"(p));
    return a;
}
__device__ __forceinline__ void cp16(uint32_t s, const void* g) {
    asm volatile("cp.async.cg.shared.global [%0], [%1], 16;" :: "r"(s), "l"(g));
}
__device__ __forceinline__ void cp_commit() {
    asm volatile("cp.async.commit_group;");
}
__device__ __forceinline__ void cp_wait1() {
    asm volatile("cp.async.wait_group 1;" ::: "memory");
}
__device__ __forceinline__ void cp_wait0() {
    asm volatile("cp.async.wait_group 0;" ::: "memory");
}
__device__ __forceinline__ void ldmx4(uint32_t addr, uint32_t* r) {
    asm volatile("ldmatrix.sync.aligned.m8n8.x4.shared.b16 {%0,%1,%2,%3}, [%4];"
                 : "=r"(r[0]), "=r"(r[1]), "=r"(r[2]), "=r"(r[3]) : "r"(addr));
}
__device__ __forceinline__ void mma16816h(float* c, const uint32_t* a,
                                          uint32_t b0, uint32_t b1) {
    asm volatile(
        "mma.sync.aligned.m16n8k16.row.col.f32.f16.f16.f32 "
        "{%0,%1,%2,%3}, {%4,%5,%6,%7}, {%8,%9}, {%0,%1,%2,%3};"
        : "+f"(c[0]), "+f"(c[1]), "+f"(c[2]), "+f"(c[3])
        : "r"(a[0]), "r"(a[1]), "r"(a[2]), "r"(a[3]), "r"(b0), "r"(b1));
}

// ---------------------------------------------------------------------------
// B prep: g_B[co][k*288+q*72+j] from weights/W_lrf/b_lrf.
// grid (15,4,2), 128 threads (thread = one co), 64KB dyn smem slab.
//   j<32:   weights[k][q*64+j][co]
//   j=32+t: sum_c W_lrf[t][c]*weights[k][q*64+32+c][co]    (t<36)
//   j=68:   sum_c b_lrf[c]*weights[k][q*64+32+c][co]
//   j>68:   0
// ---------------------------------------------------------------------------
__global__ __launch_bounds__(128) void bprep_kernel(
    const float* __restrict__ W,       // [15][256][256]
    const float* __restrict__ W_lrf,   // [36][32]
    const float* __restrict__ b_lrf)   // [32]
{
    extern __shared__ float s[];       // [64][256]
    __shared__ float Wl[36 * 32];
    __shared__ float bl[32];

    const int k   = blockIdx.x;
    const int q   = blockIdx.y;
    const int co  = blockIdx.z * 128 + threadIdx.x;
    const int tid = threadIdx.x;

    for (int i = tid; i < 36 * 32; i += 128) Wl[i] = W_lrf[i];
    if (tid < 32) bl[tid] = b_lrf[tid];

    // load 64x256 slice coalesced
    const float* Wb = W + ((size_t)k * 256 + q * 64) * 256;
    for (int i = tid; i < 64 * 256 / 4; i += 128) {
        reinterpret_cast<float4*>(s)[i] =
            reinterpret_cast<const float4*>(Wb)[i];
    }
    __syncthreads();

    float acc[37];
    #pragma unroll
    for (int t = 0; t < 37; t++) acc[t] = 0.0f;

    #pragma unroll 4
    for (int c = 0; c < 32; c++) {
        const float sv = s[(32 + c) * 256 + co];
        #pragma unroll
        for (int t = 0; t < 36; t++) acc[t] += Wl[t * 32 + c] * sv;
        acc[36] += bl[c] * sv;
    }

    __half h[72];
    #pragma unroll
    for (int j = 0; j < 32; j++) h[j] = __float2half_rn(s[j * 256 + co]);
    #pragma unroll
    for (int t = 0; t < 37; t++) h[32 + t] = __float2half_rn(acc[t]);
    h[69] = __float2half_rn(0.f); h[70] = h[69]; h[71] = h[69];

    __half* dst = &g_B[(size_t)co * BIGK2 + k * KROW + q * QW];
    #pragma unroll
    for (int v = 0; v < 9; v++)
        reinterpret_cast<uint4*>(dst)[v] = reinterpret_cast<const uint4*>(h)[v];
}

// ---------------------------------------------------------------------------
// Stage 1: per-query geometry + neighbor reduction. 160 threads/block.
// ---------------------------------------------------------------------------
__global__ __launch_bounds__(160) void stage1_kernel(
    const float* __restrict__ q_pts,
    const float* __restrict__ s_pts,
    const int*   __restrict__ neighb_inds,
    const float* __restrict__ x,
    const float* __restrict__ q_lrf,
    const float* __restrict__ s_lrf,
    const float* __restrict__ kpts)
{
    __shared__ __align__(16) float ql[36];
    __shared__ __align__(16) float kp_s[48];
    __shared__ __align__(16) float w_sm[16 * 120];   // [k][m*4+q], k=15 pad
    __shared__ __align__(16) float f_sm[30 * KROW];  // [m][q*72 + j]
    __shared__ int   ind_s[30];
    __shared__ float qp[3];

    const int n   = blockIdx.x;
    const int tid = threadIdx.x;

    if (tid < 36) ql[tid]    = q_lrf[(size_t)n * 36 + tid];
    if (tid < 45) kp_s[tid]  = kpts[tid];
    if (tid < 3)  qp[tid]    = q_pts[(size_t)n * 3 + tid];
    if (tid < 30) ind_s[tid] = neighb_inds[(size_t)n * NEI + tid];
    if (tid < 120) w_sm[15 * 120 + tid] = 0.0f;
    __syncthreads();

    // x gather into j<32 slots
    #pragma unroll 1
    for (int i = tid; i < NEI * CIN_; i += 160) {
        const int m  = i >> 7;
        const int qc = i & 127;
        const int ind = ind_s[m];
        float v = 0.0f;
        if (ind < S_SUP) v = x[(size_t)ind * CIN_ + qc];
        f_sm[m * KROW + (qc >> 5) * QW + (qc & 31)] = v;
    }

    // per-(m,q) geometry
    if (tid < 120) {
        const int m = tid >> 2;
        const int q = tid & 3;
        const int ind = ind_s[m];
        const bool valid = (ind < S_SUP);
        const int indc = valid ? ind : 0;
        const float* qlr = &ql[q * 9];

        const float nb0 = s_pts[(size_t)indc * 3 + 0] - qp[0];
        const float nb1 = s_pts[(size_t)indc * 3 + 1] - qp[1];
        const float nb2 = s_pts[(size_t)indc * 3 + 2] - qp[2];
        const float a0 = nb0 * qlr[0] + nb1 * qlr[3] + nb2 * qlr[6];
        const float a1 = nb0 * qlr[1] + nb1 * qlr[4] + nb2 * qlr[7];
        const float a2 = nb0 * qlr[2] + nb1 * qlr[5] + nb2 * qlr[8];

        #pragma unroll
        for (int k = 0; k < KP; k++) {
            const float d0 = a0 - kp_s[k * 3 + 0];
            const float d1 = a1 - kp_s[k * 3 + 1];
            const float d2 = a2 - kp_s[k * 3 + 2];
            float w = 1.0f - sqrtf(d0 * d0 + d1 * d1 + d2 * d2) * INV_EXT;
            w = fmaxf(w, 0.0f);
            w_sm[k * 120 + m * 4 + q] = valid ? w : 0.0f;
        }

        float sl[36];
        {
            const float4* p = reinterpret_cast<const float4*>(s_lrf + (size_t)indc * 36);
            #pragma unroll
            for (int t = 0; t < 9; t++) {
                const float4 v = p[t];
                sl[t * 4 + 0] = v.x; sl[t * 4 + 1] = v.y;
                sl[t * 4 + 2] = v.z; sl[t * 4 + 3] = v.w;
            }
        }
        float* fr = &f_sm[m * KROW + q * QW];
        #pragma unroll
        for (int s = 0; s < 4; s++)
            #pragma unroll
            for (int i = 0; i < 3; i++)
                #pragma unroll
                for (int j = 0; j < 3; j++) {
                    fr[32 + s * 9 + i * 3 + j] =
                        qlr[0 * 3 + i] * sl[s * 9 + 0 * 3 + j] +
                        qlr[1 * 3 + i] * sl[s * 9 + 1 * 3 + j] +
                        qlr[2 * 3 + i] * sl[s * 9 + 2 * 3 + j];
                }
        fr[68] = valid ? 1.0f : 0.0f;
        fr[69] = 0.0f; fr[70] = 0.0f; fr[71] = 0.0f;
    }
    __syncthreads();

    // phase 2: A[q,k,j] = sum_m w[q,k,m] * f[m,q,j]
    // 144 tasks on 160 threads (single pass): (h,q,c17), 8 k x float4 each.
    if (tid < 144) {
        const int c17 = tid % 18;
        const int rem = tid / 18;
        const int q2  = rem & 3;
        const int h   = rem >> 2;
        const int k0  = h * 8;

        float4 acc[8];
        #pragma unroll
        for (int i = 0; i < 8; i++) acc[i] = make_float4(0.f, 0.f, 0.f, 0.f);

        #pragma unroll 1
        for (int m = 0; m < NEI; m++) {
            const float4 f4 = *reinterpret_cast<const float4*>(
                &f_sm[m * KROW + q2 * QW + c17 * 4]);
            const float* wp = &w_sm[k0 * 120 + m * 4 + q2];
            #pragma unroll
            for (int kl = 0; kl < 8; kl++) {
                const float wv = wp[kl * 120];
                acc[kl].x += wv * f4.x; acc[kl].y += wv * f4.y;
                acc[kl].z += wv * f4.z; acc[kl].w += wv * f4.w;
            }
        }

        #pragma unroll
        for (int kl = 0; kl < 8; kl++) {
            const int k = k0 + kl;
            if (k < KP) {
                const size_t off = (size_t)n * BIGK2 + k * KROW + q2 * QW + c17 * 4;
                __half2 p0 = __floats2half2_rn(acc[kl].x, acc[kl].y);
                __half2 p1 = __floats2half2_rn(acc[kl].z, acc[kl].w);
                uint2 pk;
                pk.x = *reinterpret_cast<uint32_t*>(&p0);
                pk.y = *reinterpret_cast<uint32_t*>(&p1);
                *reinterpret_cast<uint2*>(&g_A[off]) = pk;
            }
        }
    }
}

// ---------------------------------------------------------------------------
// Stage 2: fp16 mma.sync GEMM. CTA 128x128, BK=32, 4 warps (64x64 tiles).
// ---------------------------------------------------------------------------
__global__ __launch_bounds__(128)
void gemm_mma_kernel(const float* __restrict__ bias, float* __restrict__ C)
{
    extern __shared__ __align__(16) char sm[];
    const uint32_t s0 = smem_u32(sm);

    const int tid  = threadIdx.x;
    const int wid  = tid >> 5;
    const int lane = tid & 31;
    const int r0   = blockIdx.x * BM;
    const int c0   = blockIdx.y * BN;

    const int wm = (wid & 1) * 64;
    const int wn = (wid >> 1) * 64;

    float acc[4][8][4];
    #pragma unroll
    for (int i = 0; i < 4; i++)
        #pragma unroll
        for (int j = 0; j < 8; j++)
            #pragma unroll
            for (int e = 0; e < 4; e++) acc[i][j][e] = 0.0f;

    auto load_chunk = [&](int c, int buf) {
        const int kc = c * BK;
        const uint32_t base = s0 + buf * BUF_BYTES;
        #pragma unroll
        for (int it = 0; it < 4; it++) {
            const int i   = tid + it * 128;          // 0..511
            const int row = i >> 2;
            const int kq  = (i & 3) * 8;
            const uint32_t so = row * (LDS_ * 2) + kq * 2;
            cp16(base + so, &g_A[(size_t)(r0 + row) * BIGK2 + kc + kq]);
            cp16(base + MAT_BYTES + so, &g_B[(size_t)(c0 + row) * BIGK2 + kc + kq]);
        }
        cp_commit();
    };

    const int a_row = lane & 15;
    const int a_kof = (lane >> 4) * 8;
    const int b_nof = ((lane >> 4) * 8) + (lane & 7);
    const int b_kof = ((lane >> 3) & 1) * 8;

    load_chunk(0, 0);

    for (int c = 0; c < NKC; c++) {
        const int buf = c & 1;
        if (c + 1 < NKC) { load_chunk(c + 1, buf ^ 1); cp_wait1(); }
        else             { cp_wait0(); }
        __syncthreads();

        const uint32_t bA = s0 + buf * BUF_BYTES;
        const uint32_t bB = bA + MAT_BYTES;

        #pragma unroll
        for (int ks = 0; ks < 2; ks++) {
            const int k16 = ks * 16;
            uint32_t aH[4][4], bH[8][2];

            #pragma unroll
            for (int mt = 0; mt < 4; mt++) {
                const uint32_t off =
                    (wm + mt * 16 + a_row) * (LDS_ * 2) + (k16 + a_kof) * 2;
                ldmx4(bA + off, aH[mt]);
            }
            #pragma unroll
            for (int np = 0; np < 4; np++) {
                const uint32_t off =
                    (wn + np * 16 + b_nof) * (LDS_ * 2) + (k16 + b_kof) * 2;
                uint32_t t[4];
                ldmx4(bB + off, t);
                bH[np * 2 + 0][0] = t[0]; bH[np * 2 + 0][1] = t[1];
                bH[np * 2 + 1][0] = t[2]; bH[np * 2 + 1][1] = t[3];
            }

            #pragma unroll
            for (int mt = 0; mt < 4; mt++)
                #pragma unroll
                for (int nt = 0; nt < 8; nt++)
                    mma16816h(acc[mt][nt], aH[mt], bH[nt][0], bH[nt][1]);
        }
        __syncthreads();
    }

    // epilogue: bias + LeakyReLU
    const int erow = lane >> 2;
    const int ecol = (lane & 3) * 2;
    #pragma unroll
    for (int nt = 0; nt < 8; nt++) {
        const int col = c0 + wn + nt * 8 + ecol;
        const float b0 = bias[col], b1 = bias[col + 1];
        #pragma unroll
        for (int mt = 0; mt < 4; mt++) {
            #pragma unroll
            for (int h = 0; h < 2; h++) {
                const int row = r0 + wm + mt * 16 + erow + h * 8;
                if (row < N_Q) {
                    float v0 = acc[mt][nt][h * 2 + 0] + b0;
                    float v1 = acc[mt][nt][h * 2 + 1] + b1;
                    v0 = (v0 >= 0.f) ? v0 : 0.1f * v0;
                    v1 = (v1 >= 0.f) ? v1 : 0.1f * v1;
                    *reinterpret_cast<float2*>(&C[(size_t)row * COUT_ + col]) =
                        make_float2(v0, v1);
                }
            }
        }
    }
}

// ---------------------------------------------------------------------------
// Launch
// ---------------------------------------------------------------------------
extern "C" void kernel_launch(void* const* d_in, const int* in_sizes, int n_in,
                              void* d_out, int out_size) {
    const float* q_pts   = (const float*)d_in[0];
    const float* s_pts   = (const float*)d_in[1];
    const int*   inds    = (const int*)  d_in[2];
    const float* x       = (const float*)d_in[3];
    const float* q_lrf   = (const float*)d_in[4];
    const float* s_lrf   = (const float*)d_in[5];
    const float* kpts    = (const float*)d_in[6];
    const float* weights = (const float*)d_in[7];
    const float* W_lrf   = (const float*)d_in[8];
    const float* b_lrf   = (const float*)d_in[9];
    const float* bias    = (const float*)d_in[10];
    float* out = (float*)d_out;

    cudaFuncSetAttribute(bprep_kernel,
                         cudaFuncAttributeMaxDynamicSharedMemorySize, 65536);
    cudaFuncSetAttribute(gemm_mma_kernel,
                         cudaFuncAttributeMaxDynamicSharedMemorySize, SMEM_DYN);

    bprep_kernel<<<dim3(KP, 4, 2), 128, 65536>>>(weights, W_lrf, b_lrf);

    stage1_kernel<<<N_Q, 160>>>(q_pts, s_pts, inds, x, q_lrf, s_lrf, kpts);

    dim3 ggrid(M_PAD / BM, COUT_ / BN);
    gemm_mma_kernel<<<ggrid, 128, SMEM_DYN>>>(bias, out);
}